// round 7
// baseline (speedup 1.0000x reference)
#include <cuda_runtime.h>
#include <cstdint>

#define BB 4
#define SS 2048
#define EE 1024
#define HH 16
#define DD 64
#define MROWS (BB * SS)   // 8192
#define L2E 1.4426950408889634f

// Scratch (device globals: allocation-free rule)
__device__ float g_q[BB * HH * SS * DD];    // tf32-rounded, scaled by 1/8, +bias
__device__ float g_khi[BB * HH * SS * DD];  // tf32 hi part of k (+bias)
__device__ float g_klo[BB * HH * SS * DD];  // tf32 lo part of k
__device__ float g_v[BB * HH * SS * DD];    // tf32-rounded v (+bias)
__device__ float g_att[BB * SS * EE];       // attention out, tf32-rounded
__device__ float g_xa[MROWS * EE];          // x, tf32-rounded
__device__ float g_wqkv[3 * EE * EE];       // qkv_w, tf32-rounded
__device__ float g_wout[EE * EE];           // out_w, tf32-rounded

// ---------------------------------------------------------------------------
__device__ __forceinline__ uint32_t f2tf32(float f) {
    uint32_t u;
    asm("cvt.rna.tf32.f32 %0, %1;" : "=r"(u) : "f"(f));
    return u;
}

__device__ __forceinline__ void mma8(float* c,
                                     uint32_t a0, uint32_t a1, uint32_t a2, uint32_t a3,
                                     uint32_t b0, uint32_t b1) {
    asm volatile(
        "mma.sync.aligned.m16n8k8.row.col.f32.tf32.tf32.f32 "
        "{%0,%1,%2,%3}, {%4,%5,%6,%7}, {%8,%9}, {%0,%1,%2,%3};"
        : "+f"(c[0]), "+f"(c[1]), "+f"(c[2]), "+f"(c[3])
        : "r"(a0), "r"(a1), "r"(a2), "r"(a3), "r"(b0), "r"(b1));
}

__device__ __forceinline__ void cpa16(uint32_t dst, const void* src) {
    asm volatile("cp.async.cg.shared.global [%0], [%1], 16;"
                 :: "r"(dst), "l"(src));
}
#define CP_COMMIT() asm volatile("cp.async.commit_group;" ::: "memory")
#define CP_WAIT(n)  asm volatile("cp.async.wait_group %0;" :: "n"(n) : "memory")

// fast exp2 on fma pipe (no MUFU bottleneck)
__device__ __forceinline__ float fexp2(float x) {
    x = fmaxf(x, -125.0f);
    const int ei = __float2int_rn(x);
    const float f = x - (float)ei;
    float p = fmaf(f, 0.0096181291f, 0.0555041087f);
    p = fmaf(f, p, 0.2402264923f);
    p = fmaf(f, p, 0.6931471806f);
    p = fmaf(f, p, 1.0f);
    return p * __int_as_float((ei + 127) << 23);
}

// ---------------------------------------------------------------------------
// prep: tf32-round (RNA) a float array into a scratch global
// ---------------------------------------------------------------------------
__global__ __launch_bounds__(256) void cvt_kernel(const float4* __restrict__ src,
                                                  float4* __restrict__ dst, int n4)
{
    const int i = blockIdx.x * blockDim.x + threadIdx.x;
    if (i < n4) {
        float4 v = src[i];
        float4 o;
        o.x = __uint_as_float(f2tf32(v.x));
        o.y = __uint_as_float(f2tf32(v.y));
        o.z = __uint_as_float(f2tf32(v.z));
        o.w = __uint_as_float(f2tf32(v.w));
        dst[i] = o;
    }
}

// ===========================================================================
// tf32 mma.sync GEMM: C[M,N] = A[M,K=1024] @ W[N,K]^T + bias
// A and W already tf32-rounded. CTA tile 128x256, 8 warps (2x4) of 64x64,
// k-chunk 16, 3-stage cp.async pipeline, zero conversions in loop.
// MODE 0: A = g_xa, W = g_wqkv -> g_q (scaled) / g_khi+g_klo / g_v
// MODE 1: A = g_att, W = g_wout -> Cp with bias
// ===========================================================================
#define LDT 20
#define ASZ (128 * LDT)
#define BSZ (256 * LDT)
#define NST 3
#define GEMM_SMEM (NST * (ASZ + BSZ) * 4)   // 92160 B

template <int MODE>
__global__ __launch_bounds__(256, 1) void gemm_mma(
    const float* __restrict__ bias, float* __restrict__ Cp, int N)
{
    extern __shared__ uint32_t sm[];
    uint32_t sm_u32;
    asm("{ .reg .u64 t; cvta.to.shared.u64 t, %1; cvt.u32.u64 %0, t; }"
        : "=r"(sm_u32) : "l"(sm));

    const float* A = (MODE == 1) ? (const float*)g_att : (const float*)g_xa;
    const float* W = (MODE == 1) ? (const float*)g_wout : (const float*)g_wqkv;

    const int tid = threadIdx.x, lane = tid & 31, wid = tid >> 5;
    const int bm = blockIdx.y, bn = blockIdx.x;
    const int wm = wid >> 2, wn = wid & 3;
    const int gr = lane >> 2, tc = lane & 3;

    const float4* Ag = (const float4*)A + (size_t)(bm * 128) * 256;
    const float4* Wg = (const float4*)W + (size_t)(bn * 256) * 256;

    float acc[4][8][4];
#pragma unroll
    for (int i = 0; i < 4; ++i)
#pragma unroll
        for (int j = 0; j < 8; ++j)
#pragma unroll
            for (int t = 0; t < 4; ++t) acc[i][j][t] = 0.f;

    // cp.async issue of one k-stage (A: 2x16B, B: 4x16B per thread)
#define ISSUE(stg, kt)                                                        \
    do {                                                                      \
        _Pragma("unroll")                                                     \
        for (int t = 0; t < 2; ++t) {                                         \
            const int f = tid + t * 256;                                      \
            const uint32_t d = sm_u32 +                                       \
                ((stg) * ASZ + (f >> 2) * LDT + (f & 3) * 4) * 4;             \
            cpa16(d, Ag + (size_t)(f >> 2) * 256 + (kt) * 4 + (f & 3));       \
        }                                                                     \
        _Pragma("unroll")                                                     \
        for (int t = 0; t < 4; ++t) {                                         \
            const int f = tid + t * 256;                                      \
            const uint32_t d = sm_u32 +                                       \
                (NST * ASZ + (stg) * BSZ + (f >> 2) * LDT + (f & 3) * 4) * 4; \
            cpa16(d, Wg + (size_t)(f >> 2) * 256 + (kt) * 4 + (f & 3));       \
        }                                                                     \
        CP_COMMIT();                                                          \
    } while (0)

    ISSUE(0, 0);
    ISSUE(1, 1);

    for (int kt = 0; kt < 64; ++kt) {
        CP_WAIT(1);
        __syncthreads();

        const uint32_t* as = sm + (kt % NST) * ASZ;
        const uint32_t* bs = sm + NST * ASZ + (kt % NST) * BSZ;
#pragma unroll
        for (int kk = 0; kk < 16; kk += 8) {
            uint32_t af[4][4], bf[8][2];
#pragma unroll
            for (int mi = 0; mi < 4; ++mi) {
                const int rb = (wm * 64 + mi * 16 + gr) * LDT + kk + tc;
                af[mi][0] = as[rb];
                af[mi][1] = as[rb + 8 * LDT];
                af[mi][2] = as[rb + 4];
                af[mi][3] = as[rb + 8 * LDT + 4];
            }
#pragma unroll
            for (int ni = 0; ni < 8; ++ni) {
                const int cb = (wn * 64 + ni * 8 + gr) * LDT + kk + tc;
                bf[ni][0] = bs[cb];
                bf[ni][1] = bs[cb + 4];
            }
#pragma unroll
            for (int mi = 0; mi < 4; ++mi)
#pragma unroll
                for (int ni = 0; ni < 8; ++ni)
                    mma8(acc[mi][ni], af[mi][0], af[mi][1], af[mi][2], af[mi][3],
                         bf[ni][0], bf[ni][1]);
        }
        __syncthreads();
        if (kt + 2 < 64) {
            ISSUE((kt + 2) % NST, kt + 2);
        } else {
            CP_COMMIT();
        }
    }
#undef ISSUE

    // ---------------- epilogue ----------------
    if (MODE == 1) {
#pragma unroll
        for (int mi = 0; mi < 4; ++mi)
#pragma unroll
            for (int rr = 0; rr < 2; ++rr) {
                const int row = bm * 128 + wm * 64 + mi * 16 + rr * 8 + gr;
#pragma unroll
                for (int ni = 0; ni < 8; ++ni) {
                    const int col = bn * 256 + wn * 64 + ni * 8 + 2 * tc;
                    float2 o;
                    o.x = acc[mi][ni][rr * 2]     + bias[col];
                    o.y = acc[mi][ni][rr * 2 + 1] + bias[col + 1];
                    *(float2*)(Cp + (size_t)row * N + col) = o;
                }
            }
    } else {
        const int cgw = bn * 4 + wn;            // 0..47: one (head,part) / warp
        const int h = cgw / 3, cpart = cgw % 3;
        float* dstb = (cpart == 0) ? g_q : (cpart == 1) ? g_khi : g_v;
#pragma unroll
        for (int mi = 0; mi < 4; ++mi)
#pragma unroll
            for (int rr = 0; rr < 2; ++rr) {
                const int row = bm * 128 + wm * 64 + mi * 16 + rr * 8 + gr;
                const int b = row >> 11, s = row & 2047;
                const size_t ro = ((size_t)(b * HH + h) * SS + s) << 6;
#pragma unroll
                for (int ni = 0; ni < 8; ++ni) {
                    const int col = bn * 256 + wn * 64 + ni * 8 + 2 * tc;
                    const int d = ni * 8 + 2 * tc;
                    float v0 = acc[mi][ni][rr * 2]     + bias[col];
                    float v1 = acc[mi][ni][rr * 2 + 1] + bias[col + 1];
                    if (cpart == 0) { v0 *= 0.125f; v1 *= 0.125f; }
                    const uint32_t h0 = f2tf32(v0), h1 = f2tf32(v1);
                    float2 o;
                    o.x = __uint_as_float(h0);
                    o.y = __uint_as_float(h1);
                    *(float2*)(dstb + ro + d) = o;
                    if (cpart == 1) {
                        float2 lo;
                        lo.x = __uint_as_float(f2tf32(v0 - __uint_as_float(h0)));
                        lo.y = __uint_as_float(f2tf32(v1 - __uint_as_float(h1)));
                        *(float2*)(g_klo + ro + d) = lo;
                    }
                }
            }
    }
}

// ===========================================================================
// Tensor-core causal flash attention (R5 structure; epilogue rounds to tf32).
// ===========================================================================
#define VST 72
#define ATTN_SMEM ((4352 + 4352 + 64 * VST + 4 * 2176) * 4)   // 88064 B

__global__ __launch_bounds__(128, 2) void attn_mma()
{
    extern __shared__ uint32_t smm[];
    uint32_t* Khi = smm;                        // [64][68]
    uint32_t* Klo = smm + 4352;                 // [64][68]
    uint32_t* Vs  = smm + 8704;                 // [64][VST] natural layout
    const int tid = threadIdx.x, lane = tid & 31, wid = tid >> 5;
    uint32_t* Pw  = smm + 8704 + 64 * VST + wid * 2176;   // [32][68] per warp
    const int gr = lane >> 2, tc = lane & 3;
    const int bh = blockIdx.y, qt = blockIdx.x;
    const int qbase = qt * 128;
    const int wrow = qbase + wid * 32;

    const float* Qb  = g_q + ((size_t)bh * SS + wrow) * DD;
    const uint4* KH4 = (const uint4*)(g_khi + (size_t)bh * SS * DD);
    const uint4* KL4 = (const uint4*)(g_klo + (size_t)bh * SS * DD);
    const uint4* V4  = (const uint4*)(g_v   + (size_t)bh * SS * DD);

    float Oc[2][8][4];
#pragma unroll
    for (int mi = 0; mi < 2; ++mi)
#pragma unroll
        for (int ni = 0; ni < 8; ++ni)
#pragma unroll
            for (int r = 0; r < 4; ++r) Oc[mi][ni][r] = 0.f;
    float mrow[2][2] = {{-1e30f, -1e30f}, {-1e30f, -1e30f}};
    float lrow[2][2] = {{0.f, 0.f}, {0.f, 0.f}};

    const int nkt = 2 * qt + 2;
    for (int kt = 0; kt < nkt; ++kt) {
        const int kvb = kt * 64;
        __syncthreads();

#pragma unroll
        for (int j = 0; j < 8; ++j) {
            const int f = tid + j * 128;
            const int r = f >> 4, c4 = f & 15;
            *(uint4*)(Khi + r * 68 + c4 * 4) = KH4[kvb * 16 + f];
            *(uint4*)(Klo + r * 68 + c4 * 4) = KL4[kvb * 16 + f];
            *(uint4*)(Vs + r * VST + c4 * 4) = V4[kvb * 16 + f];
        }
        __syncthreads();

        if (kvb > wrow + 31) continue;

        float sc[2][8][4];
#pragma unroll
        for (int mi = 0; mi < 2; ++mi)
#pragma unroll
            for (int ni = 0; ni < 8; ++ni)
#pragma unroll
                for (int r = 0; r < 4; ++r) sc[mi][ni][r] = 0.f;

#pragma unroll
        for (int kk = 0; kk < 8; ++kk) {
            uint32_t qa[2][4];
#pragma unroll
            for (int mi = 0; mi < 2; ++mi) {
                const float* qp = Qb + (mi * 16 + gr) * DD + kk * 8 + tc;
                qa[mi][0] = __float_as_uint(qp[0]);
                qa[mi][1] = __float_as_uint(qp[8 * DD]);
                qa[mi][2] = __float_as_uint(qp[4]);
                qa[mi][3] = __float_as_uint(qp[8 * DD + 4]);
            }
            uint32_t bhv[8][2], blv[8][2];
#pragma unroll
            for (int ni = 0; ni < 8; ++ni) {
                const int ba = (ni * 8 + gr) * 68 + kk * 8 + tc;
                bhv[ni][0] = Khi[ba]; bhv[ni][1] = Khi[ba + 4];
                blv[ni][0] = Klo[ba]; blv[ni][1] = Klo[ba + 4];
            }
#pragma unroll
            for (int mi = 0; mi < 2; ++mi)
#pragma unroll
                for (int ni = 0; ni < 8; ++ni) {
                    mma8(sc[mi][ni], qa[mi][0], qa[mi][1], qa[mi][2], qa[mi][3],
                         bhv[ni][0], bhv[ni][1]);
                    mma8(sc[mi][ni], qa[mi][0], qa[mi][1], qa[mi][2], qa[mi][3],
                         blv[ni][0], blv[ni][1]);
                }
        }

        if (kvb + 63 > qbase) {
#pragma unroll
            for (int mi = 0; mi < 2; ++mi)
#pragma unroll
                for (int ni = 0; ni < 8; ++ni)
#pragma unroll
                    for (int r = 0; r < 4; ++r) {
                        const int i = wrow + mi * 16 + gr + (r >> 1) * 8;
                        const int j = kvb + ni * 8 + 2 * tc + (r & 1);
                        if (j > i) sc[mi][ni][r] = -1e30f;
                    }
        }

#pragma unroll
        for (int mi = 0; mi < 2; ++mi)
#pragma unroll
            for (int rr = 0; rr < 2; ++rr) {
                float mx = -1e30f;
#pragma unroll
                for (int ni = 0; ni < 8; ++ni)
                    mx = fmaxf(mx, fmaxf(sc[mi][ni][rr * 2], sc[mi][ni][rr * 2 + 1]));
                mx = fmaxf(mx, __shfl_xor_sync(0xffffffffu, mx, 1));
                mx = fmaxf(mx, __shfl_xor_sync(0xffffffffu, mx, 2));
                const float mnew = fmaxf(mrow[mi][rr], mx);
                const float corr = fexp2((mrow[mi][rr] - mnew) * L2E);
                mrow[mi][rr] = mnew;
                const float mL = mnew * L2E;
                float rs = 0.f;
#pragma unroll
                for (int ni = 0; ni < 8; ++ni) {
                    const float p0 = fexp2(fmaf(sc[mi][ni][rr * 2],     L2E, -mL));
                    const float p1 = fexp2(fmaf(sc[mi][ni][rr * 2 + 1], L2E, -mL));
                    rs += p0 + p1;
                    Oc[mi][ni][rr * 2]     *= corr;
                    Oc[mi][ni][rr * 2 + 1] *= corr;
                    uint2 pp;
                    pp.x = f2tf32(p0);
                    pp.y = f2tf32(p1);
                    *(uint2*)(Pw + (mi * 16 + rr * 8 + gr) * 68 + ni * 8 + 2 * tc) = pp;
                }
                rs += __shfl_xor_sync(0xffffffffu, rs, 1);
                rs += __shfl_xor_sync(0xffffffffu, rs, 2);
                lrow[mi][rr] = lrow[mi][rr] * corr + rs;
            }
        __syncwarp();

#pragma unroll
        for (int kk = 0; kk < 8; ++kk) {
            uint32_t pf[2][4], vfv[8][2];
#pragma unroll
            for (int mi = 0; mi < 2; ++mi) {
                const int pa = (mi * 16 + gr) * 68 + kk * 8 + tc;
                pf[mi][0] = Pw[pa];
                pf[mi][1] = Pw[pa + 8 * 68];
                pf[mi][2] = Pw[pa + 4];
                pf[mi][3] = Pw[pa + 8 * 68 + 4];
            }
#pragma unroll
            for (int ni = 0; ni < 8; ++ni) {
                vfv[ni][0] = Vs[(kk * 8 + tc) * VST + ni * 8 + gr];
                vfv[ni][1] = Vs[(kk * 8 + tc + 4) * VST + ni * 8 + gr];
            }
#pragma unroll
            for (int mi = 0; mi < 2; ++mi)
#pragma unroll
                for (int ni = 0; ni < 8; ++ni)
                    mma8(Oc[mi][ni], pf[mi][0], pf[mi][1], pf[mi][2], pf[mi][3],
                         vfv[ni][0], vfv[ni][1]);
        }
    }

    // ---- normalize + store tf32-rounded to g_att [B,S,E] ----
    const int b = bh >> 4, hh = bh & 15;
#pragma unroll
    for (int mi = 0; mi < 2; ++mi)
#pragma unroll
        for (int rr = 0; rr < 2; ++rr) {
            const float inv = 1.0f / lrow[mi][rr];
            const int row = wrow + mi * 16 + rr * 8 + gr;
            float* og = g_att + (size_t)(b * SS + row) * EE + hh * 64;
#pragma unroll
            for (int ni = 0; ni < 8; ++ni) {
                float2 o;
                o.x = __uint_as_float(f2tf32(Oc[mi][ni][rr * 2]     * inv));
                o.y = __uint_as_float(f2tf32(Oc[mi][ni][rr * 2 + 1] * inv));
                *(float2*)(og + ni * 8 + 2 * tc) = o;
            }
        }
}

// ---------------------------------------------------------------------------
extern "C" void kernel_launch(void* const* d_in, const int* in_sizes, int n_in,
                              void* d_out, int out_size)
{
    const float* x     = (const float*)d_in[0];
    const float* qkv_w = (const float*)d_in[1];
    const float* qkv_b = (const float*)d_in[2];
    const float* out_w = (const float*)d_in[3];
    const float* out_b = (const float*)d_in[4];
    float* out = (float*)d_out;

    cudaFuncSetAttribute(gemm_mma<0>, cudaFuncAttributeMaxDynamicSharedMemorySize, GEMM_SMEM);
    cudaFuncSetAttribute(gemm_mma<1>, cudaFuncAttributeMaxDynamicSharedMemorySize, GEMM_SMEM);
    cudaFuncSetAttribute(attn_mma, cudaFuncAttributeMaxDynamicSharedMemorySize, ATTN_SMEM);

    float* xa; float* wq; float* wo;
    cudaGetSymbolAddress((void**)&xa, g_xa);
    cudaGetSymbolAddress((void**)&wq, g_wqkv);
    cudaGetSymbolAddress((void**)&wo, g_wout);

    // 0) tf32-round inputs (keeps GEMM loop conversion-free)
    cvt_kernel<<<(MROWS * EE / 4 + 255) / 256, 256>>>((const float4*)x, (float4*)xa, MROWS * EE / 4);
    cvt_kernel<<<(3 * EE * EE / 4 + 255) / 256, 256>>>((const float4*)qkv_w, (float4*)wq, 3 * EE * EE / 4);
    cvt_kernel<<<(EE * EE / 4 + 255) / 256, 256>>>((const float4*)out_w, (float4*)wo, EE * EE / 4);

    // 1) fused QKV projection -> g_q (tf32,scaled) / g_khi,g_klo / g_v
    gemm_mma<0><<<dim3(3072 / 256, MROWS / 128), 256, GEMM_SMEM>>>(qkv_b, nullptr, 3 * EE);

    // 2) causal flash attention -> g_att (tf32-rounded)
    attn_mma<<<dim3(SS / 128, BB * HH), 128, ATTN_SMEM>>>();

    // 3) output projection
    gemm_mma<1><<<dim3(EE / 256, MROWS / 128), 256, GEMM_SMEM>>>(out_b, out, EE);
}

// round 14
// speedup vs baseline: 2.1328x; 2.1328x over previous
#include <cuda_runtime.h>
#include <cuda_fp16.h>
#include <cstdint>

#define BB 4
#define SS 2048
#define EE 1024
#define HH 16
#define DD 64
#define MROWS (BB * SS)   // 8192
#define L2E 1.4426950408889634f

// Scratch (device globals: allocation-free rule). All fp16, 16B-aligned.
__device__ __align__(16) __half g_q[BB * HH * SS * DD];    // scaled 1/8, +bias
__device__ __align__(16) __half g_khi[BB * HH * SS * DD];  // fp16 hi of k (+bias)
__device__ __align__(16) __half g_klo[BB * HH * SS * DD];  // fp16 residual of k
__device__ __align__(16) __half g_v[BB * HH * SS * DD];    // v (+bias)
__device__ __align__(16) __half g_att[BB * SS * EE];       // attention out
__device__ __align__(16) __half g_xa[MROWS * EE];          // x
__device__ __align__(16) __half g_wqkv[3 * EE * EE];       // qkv_w
__device__ __align__(16) __half g_wout[EE * EE];           // out_w

// ---------------------------------------------------------------------------
__device__ __forceinline__ void mma16(float* c,
                                      uint32_t a0, uint32_t a1, uint32_t a2, uint32_t a3,
                                      uint32_t b0, uint32_t b1) {
    asm volatile(
        "mma.sync.aligned.m16n8k16.row.col.f32.f16.f16.f32 "
        "{%0,%1,%2,%3}, {%4,%5,%6,%7}, {%8,%9}, {%0,%1,%2,%3};"
        : "+f"(c[0]), "+f"(c[1]), "+f"(c[2]), "+f"(c[3])
        : "r"(a0), "r"(a1), "r"(a2), "r"(a3), "r"(b0), "r"(b1));
}

__device__ __forceinline__ void cpa16(uint32_t dst, const void* src) {
    asm volatile("cp.async.cg.shared.global [%0], [%1], 16;"
                 :: "r"(dst), "l"(src));
}
#define CP_COMMIT() asm volatile("cp.async.commit_group;" ::: "memory")
#define CP_WAIT(n)  asm volatile("cp.async.wait_group %0;" :: "n"(n) : "memory")

__device__ __forceinline__ uint32_t smem_u32(const void* p) {
    uint32_t a;
    asm("{ .reg .u64 t; cvta.to.shared.u64 t, %1; cvt.u32.u64 %0, t; }"
        : "=r"(a) : "l"(p));
    return a;
}

__device__ __forceinline__ void ldsm_x4_trans(uint32_t& r0, uint32_t& r1,
                                              uint32_t& r2, uint32_t& r3,
                                              uint32_t addr) {
    asm volatile("ldmatrix.sync.aligned.m8n8.x4.trans.shared.b16 "
                 "{%0,%1,%2,%3}, [%4];"
                 : "=r"(r0), "=r"(r1), "=r"(r2), "=r"(r3) : "r"(addr));
}

// fast exp2 on fma pipe (no MUFU bottleneck)
__device__ __forceinline__ float fexp2(float x) {
    x = fmaxf(x, -125.0f);
    const int ei = __float2int_rn(x);
    const float f = x - (float)ei;
    float p = fmaf(f, 0.0096181291f, 0.0555041087f);
    p = fmaf(f, p, 0.2402264923f);
    p = fmaf(f, p, 0.6931471806f);
    p = fmaf(f, p, 1.0f);
    return p * __int_as_float((ei + 127) << 23);
}

__device__ __forceinline__ uint32_t pack2(float lo, float hi) {
    __half2 h = __floats2half2_rn(lo, hi);
    return *(uint32_t*)&h;
}

// ---------------------------------------------------------------------------
// prep: round f32 array to fp16 scratch
// ---------------------------------------------------------------------------
__global__ __launch_bounds__(256) void cvt_kernel(const float4* __restrict__ src,
                                                  __half* __restrict__ dst, int n4)
{
    const int i = blockIdx.x * blockDim.x + threadIdx.x;
    if (i < n4) {
        float4 v = src[i];
        __half2* d = (__half2*)(dst + i * 4);
        d[0] = __floats2half2_rn(v.x, v.y);
        d[1] = __floats2half2_rn(v.z, v.w);
    }
}

// ===========================================================================
// fp16 mma.sync GEMM: C[M,N] = A[M,K=1024] @ W[N,K]^T + bias
// CTA 128x128, 8 warps (2x4) of 64x32, k-chunk 32 halves, 3-stage cp.async.
// smem rows stride 40 halves (20 words; conflict-free fragment LDS).
// Staging: 4 threads/row x 16B, two row-groups -> full 128x16-word coverage.
// MODE 0: -> g_q (scaled) / g_khi+g_klo / g_v  (fp16)
// MODE 1: -> Cp (f32) with bias
// ===========================================================================
#define LDW 20                      // words per row
#define ASZW (128 * LDW)            // one stage A (words)
#define BSZW (128 * LDW)
#define NST 3
#define GEMM_SMEM (NST * (ASZW + BSZW) * 4)   // 61440 B

template <int MODE>
__global__ __launch_bounds__(256, 2) void gemm_mma(
    const float* __restrict__ bias, float* __restrict__ Cp, int N)
{
    extern __shared__ uint32_t sm[];
    const uint32_t sm_b = smem_u32(sm);

    const __half* A = (MODE == 1) ? g_att : g_xa;
    const __half* W = (MODE == 1) ? g_wout : g_wqkv;

    const int tid = threadIdx.x, lane = tid & 31, wid = tid >> 5;
    const int bm = blockIdx.y, bn = blockIdx.x;
    const int wm = wid >> 2, wn = wid & 3;
    const int gr = lane >> 2, tc = lane & 3;

    // staging: f0 = tid (rows 0..63), f1 = tid + 256 (rows 64..127)
    const int f0 = tid, f1 = tid + 256;
    const __half* Ag0 = A + (size_t)(bm * 128 + (f0 >> 2)) * 1024 + (f0 & 3) * 8;
    const __half* Ag1 = A + (size_t)(bm * 128 + (f1 >> 2)) * 1024 + (f1 & 3) * 8;
    const __half* Wg0 = W + (size_t)(bn * 128 + (f0 >> 2)) * 1024 + (f0 & 3) * 8;
    const __half* Wg1 = W + (size_t)(bn * 128 + (f1 >> 2)) * 1024 + (f1 & 3) * 8;
    const uint32_t dA0 = sm_b + (((f0 >> 2) * LDW + (f0 & 3) * 4)) * 4;
    const uint32_t dA1 = sm_b + (((f1 >> 2) * LDW + (f1 & 3) * 4)) * 4;
    const uint32_t dB0 = dA0 + NST * ASZW * 4;
    const uint32_t dB1 = dA1 + NST * ASZW * 4;

    float acc[4][4][4];
#pragma unroll
    for (int i = 0; i < 4; ++i)
#pragma unroll
        for (int j = 0; j < 4; ++j)
#pragma unroll
            for (int t = 0; t < 4; ++t) acc[i][j][t] = 0.f;

#define ISSUE(stg, kt)                                                        \
    do {                                                                      \
        cpa16(dA0 + (stg) * ASZW * 4, Ag0 + (kt) * 32);                       \
        cpa16(dA1 + (stg) * ASZW * 4, Ag1 + (kt) * 32);                       \
        cpa16(dB0 + (stg) * BSZW * 4, Wg0 + (kt) * 32);                       \
        cpa16(dB1 + (stg) * BSZW * 4, Wg1 + (kt) * 32);                       \
        CP_COMMIT();                                                          \
    } while (0)

    ISSUE(0, 0);
    ISSUE(1, 1);

    for (int kt = 0; kt < 32; ++kt) {
        CP_WAIT(1);
        __syncthreads();

        const uint32_t* as = sm + (kt % NST) * ASZW;
        const uint32_t* bs = sm + NST * ASZW + (kt % NST) * BSZW;
#pragma unroll
        for (int kk = 0; kk < 2; ++kk) {
            uint32_t af[4][4], bf[4][2];
#pragma unroll
            for (int mi = 0; mi < 4; ++mi) {
                const int rb = (wm * 64 + mi * 16 + gr) * LDW + kk * 8 + tc;
                af[mi][0] = as[rb];
                af[mi][1] = as[rb + 8 * LDW];
                af[mi][2] = as[rb + 4];
                af[mi][3] = as[rb + 8 * LDW + 4];
            }
#pragma unroll
            for (int ni = 0; ni < 4; ++ni) {
                const int cb = (wn * 32 + ni * 8 + gr) * LDW + kk * 8 + tc;
                bf[ni][0] = bs[cb];
                bf[ni][1] = bs[cb + 4];
            }
#pragma unroll
            for (int mi = 0; mi < 4; ++mi)
#pragma unroll
                for (int ni = 0; ni < 4; ++ni)
                    mma16(acc[mi][ni], af[mi][0], af[mi][1], af[mi][2], af[mi][3],
                          bf[ni][0], bf[ni][1]);
        }
        __syncthreads();
        if (kt + 2 < 32) {
            ISSUE((kt + 2) % NST, kt + 2);
        } else {
            CP_COMMIT();
        }
    }
#undef ISSUE

    // ---------------- epilogue ----------------
    if (MODE == 1) {
#pragma unroll
        for (int mi = 0; mi < 4; ++mi)
#pragma unroll
            for (int rr = 0; rr < 2; ++rr) {
                const int row = bm * 128 + wm * 64 + mi * 16 + rr * 8 + gr;
#pragma unroll
                for (int ni = 0; ni < 4; ++ni) {
                    const int col = bn * 128 + wn * 32 + ni * 8 + 2 * tc;
                    float2 o;
                    o.x = acc[mi][ni][rr * 2]     + bias[col];
                    o.y = acc[mi][ni][rr * 2 + 1] + bias[col + 1];
                    *(float2*)(Cp + (size_t)row * N + col) = o;
                }
            }
    } else {
        // warp covers 32 cols inside one 64-col (head,part) group
        const int cgw = bn * 2 + (wn >> 1);     // 0..47
        const int h = cgw / 3, cpart = cgw % 3;
        const int d0 = (wn & 1) * 32;
        __half* dstb = (cpart == 0) ? g_q : (cpart == 1) ? g_khi : g_v;
#pragma unroll
        for (int mi = 0; mi < 4; ++mi)
#pragma unroll
            for (int rr = 0; rr < 2; ++rr) {
                const int row = bm * 128 + wm * 64 + mi * 16 + rr * 8 + gr;
                const int b = row >> 11, s = row & 2047;
                const size_t ro = ((size_t)(b * HH + h) * SS + s) << 6;
#pragma unroll
                for (int ni = 0; ni < 4; ++ni) {
                    const int col = bn * 128 + wn * 32 + ni * 8 + 2 * tc;
                    const int d = d0 + ni * 8 + 2 * tc;
                    float v0 = acc[mi][ni][rr * 2]     + bias[col];
                    float v1 = acc[mi][ni][rr * 2 + 1] + bias[col + 1];
                    if (cpart == 0) { v0 *= 0.125f; v1 *= 0.125f; }
                    __half2 hi2 = __floats2half2_rn(v0, v1);
                    *(uint32_t*)(dstb + ro + d) = *(uint32_t*)&hi2;
                    if (cpart == 1) {
                        float l0 = v0 - __half2float(__low2half(hi2));
                        float l1 = v1 - __half2float(__high2half(hi2));
                        __half2 lo2 = __floats2half2_rn(l0, l1);
                        *(uint32_t*)(g_klo + ro + d) = *(uint32_t*)&lo2;
                    }
                }
            }
    }
}

// ===========================================================================
// fp16 tensor-core causal flash attention.
// grid = (S/128, B*H), block = 128 (4 warps x m32), KV tile 64.
// P kept IN REGISTERS (C-frag -> A-frag identity). V via ldmatrix.x4.trans.
// ===========================================================================
#define KST 72
#define VSTH 88
#define ATTN_SMEM ((64 * KST * 2 + 64 * VSTH) * 2)   // 29696 B

__global__ __launch_bounds__(128, 2) void attn_mma()
{
    extern __shared__ __half smh[];
    __half* Khi = smh;                          // [64][KST]
    __half* Klo = smh + 64 * KST;
    __half* Vs  = smh + 128 * KST;              // [64][VSTH]
    const uint32_t vs_b = smem_u32(Vs);

    const int tid = threadIdx.x, lane = tid & 31, wid = tid >> 5;
    const int gr = lane >> 2, tc = lane & 3;
    const int bh = blockIdx.y, qt = blockIdx.x;
    const int qbase = qt * 128;
    const int wrow = qbase + wid * 32;

    const __half* Kh = g_khi + (size_t)bh * SS * DD;
    const __half* Kl = g_klo + (size_t)bh * SS * DD;
    const __half* Vg = g_v   + (size_t)bh * SS * DD;

    // Q fragments in registers for the whole kernel: [mi][kk][4]
    uint32_t qa[2][4][4];
    {
        const uint32_t* Qw = (const uint32_t*)(g_q + ((size_t)bh * SS + wrow) * DD);
#pragma unroll
        for (int mi = 0; mi < 2; ++mi)
#pragma unroll
            for (int kk = 0; kk < 4; ++kk) {
                const int r0 = (mi * 16 + gr) * 32 + kk * 8 + tc;
                qa[mi][kk][0] = Qw[r0];
                qa[mi][kk][1] = Qw[r0 + 8 * 32];
                qa[mi][kk][2] = Qw[r0 + 4];
                qa[mi][kk][3] = Qw[r0 + 8 * 32 + 4];
            }
    }

    float Oc[2][8][4];
#pragma unroll
    for (int mi = 0; mi < 2; ++mi)
#pragma unroll
        for (int ni = 0; ni < 8; ++ni)
#pragma unroll
            for (int r = 0; r < 4; ++r) Oc[mi][ni][r] = 0.f;
    float mrow[2][2] = {{-1e30f, -1e30f}, {-1e30f, -1e30f}};
    float lrow[2][2] = {{0.f, 0.f}, {0.f, 0.f}};

    const int lm_row = lane & 15;
    const int lm_col = (lane >> 4) * 8;

    const int nkt = 2 * qt + 2;
    for (int kt = 0; kt < nkt; ++kt) {
        const int kvb = kt * 64;
        __syncthreads();

        // ---- cooperative copy (uint4, conflict-free) ----
#pragma unroll
        for (int j = 0; j < 4; ++j) {
            const int f = tid + j * 128;           // 0..511
            const int r = f >> 3, c = f & 7;
            *(uint4*)(Khi + r * KST + c * 8) = *(const uint4*)(Kh + (kvb + r) * DD + c * 8);
            *(uint4*)(Klo + r * KST + c * 8) = *(const uint4*)(Kl + (kvb + r) * DD + c * 8);
            *(uint4*)(Vs + r * VSTH + c * 8) = *(const uint4*)(Vg + (kvb + r) * DD + c * 8);
        }
        __syncthreads();

        if (kvb > wrow + 31) continue;

        // ---- QK^T (hi + lo split) ----
        float sc[2][8][4];
#pragma unroll
        for (int mi = 0; mi < 2; ++mi)
#pragma unroll
            for (int ni = 0; ni < 8; ++ni)
#pragma unroll
                for (int r = 0; r < 4; ++r) sc[mi][ni][r] = 0.f;

        const uint32_t* KhiW = (const uint32_t*)Khi;
        const uint32_t* KloW = (const uint32_t*)Klo;
#pragma unroll
        for (int kk = 0; kk < 4; ++kk) {
            uint32_t bhv[8][2], blv[8][2];
#pragma unroll
            for (int ni = 0; ni < 8; ++ni) {
                const int ba = (ni * 8 + gr) * (KST / 2) + kk * 8 + tc;
                bhv[ni][0] = KhiW[ba]; bhv[ni][1] = KhiW[ba + 4];
                blv[ni][0] = KloW[ba]; blv[ni][1] = KloW[ba + 4];
            }
#pragma unroll
            for (int mi = 0; mi < 2; ++mi)
#pragma unroll
                for (int ni = 0; ni < 8; ++ni) {
                    mma16(sc[mi][ni], qa[mi][kk][0], qa[mi][kk][1],
                          qa[mi][kk][2], qa[mi][kk][3], bhv[ni][0], bhv[ni][1]);
                    mma16(sc[mi][ni], qa[mi][kk][0], qa[mi][kk][1],
                          qa[mi][kk][2], qa[mi][kk][3], blv[ni][0], blv[ni][1]);
                }
        }

        // ---- causal mask ----
        if (kvb + 63 > qbase) {
#pragma unroll
            for (int mi = 0; mi < 2; ++mi)
#pragma unroll
                for (int ni = 0; ni < 8; ++ni)
#pragma unroll
                    for (int r = 0; r < 4; ++r) {
                        const int i = wrow + mi * 16 + gr + (r >> 1) * 8;
                        const int j = kvb + ni * 8 + 2 * tc + (r & 1);
                        if (j > i) sc[mi][ni][r] = -1e30f;
                    }
        }

        // ---- online softmax; P packed to fp16 A-fragments in registers ----
        uint32_t pk[2][8][2];
#pragma unroll
        for (int mi = 0; mi < 2; ++mi)
#pragma unroll
            for (int rr = 0; rr < 2; ++rr) {
                float mx = -1e30f;
#pragma unroll
                for (int ni = 0; ni < 8; ++ni)
                    mx = fmaxf(mx, fmaxf(sc[mi][ni][rr * 2], sc[mi][ni][rr * 2 + 1]));
                mx = fmaxf(mx, __shfl_xor_sync(0xffffffffu, mx, 1));
                mx = fmaxf(mx, __shfl_xor_sync(0xffffffffu, mx, 2));
                const float mnew = fmaxf(mrow[mi][rr], mx);
                const float corr = fexp2((mrow[mi][rr] - mnew) * L2E);
                mrow[mi][rr] = mnew;
                const float mL = mnew * L2E;
                float rs = 0.f;
#pragma unroll
                for (int ni = 0; ni < 8; ++ni) {
                    const float p0 = fexp2(fmaf(sc[mi][ni][rr * 2],     L2E, -mL));
                    const float p1 = fexp2(fmaf(sc[mi][ni][rr * 2 + 1], L2E, -mL));
                    rs += p0 + p1;
                    Oc[mi][ni][rr * 2]     *= corr;
                    Oc[mi][ni][rr * 2 + 1] *= corr;
                    pk[mi][ni][rr] = pack2(p0, p1);
                }
                rs += __shfl_xor_sync(0xffffffffu, rs, 1);
                rs += __shfl_xor_sync(0xffffffffu, rs, 2);
                lrow[mi][rr] = lrow[mi][rr] * corr + rs;
            }

        // ---- PV: O += P @ V  (A = pk registers; B via ldmatrix.x4.trans) ----
#pragma unroll
        for (int kk = 0; kk < 4; ++kk) {
            uint32_t vb[8][2];
#pragma unroll
            for (int np = 0; np < 4; ++np) {
                const uint32_t addr = vs_b +
                    ((kk * 16 + lm_row) * VSTH + np * 16 + lm_col) * 2;
                ldsm_x4_trans(vb[2 * np][0], vb[2 * np][1],
                              vb[2 * np + 1][0], vb[2 * np + 1][1], addr);
            }
#pragma unroll
            for (int mi = 0; mi < 2; ++mi)
#pragma unroll
                for (int ni = 0; ni < 8; ++ni)
                    mma16(Oc[mi][ni],
                          pk[mi][2 * kk][0], pk[mi][2 * kk][1],
                          pk[mi][2 * kk + 1][0], pk[mi][2 * kk + 1][1],
                          vb[ni][0], vb[ni][1]);
        }
    }

    // ---- normalize + store fp16 to g_att [B,S,E] ----
    const int b = bh >> 4, hh = bh & 15;
#pragma unroll
    for (int mi = 0; mi < 2; ++mi)
#pragma unroll
        for (int rr = 0; rr < 2; ++rr) {
            const float inv = 1.0f / lrow[mi][rr];
            const int row = wrow + mi * 16 + rr * 8 + gr;
            __half* og = g_att + (size_t)(b * SS + row) * EE + hh * 64;
#pragma unroll
            for (int ni = 0; ni < 8; ++ni) {
                __half2 o = __floats2half2_rn(Oc[mi][ni][rr * 2] * inv,
                                              Oc[mi][ni][rr * 2 + 1] * inv);
                *(uint32_t*)(og + ni * 8 + 2 * tc) = *(uint32_t*)&o;
            }
        }
}

// ---------------------------------------------------------------------------
extern "C" void kernel_launch(void* const* d_in, const int* in_sizes, int n_in,
                              void* d_out, int out_size)
{
    const float* x     = (const float*)d_in[0];
    const float* qkv_w = (const float*)d_in[1];
    const float* qkv_b = (const float*)d_in[2];
    const float* out_w = (const float*)d_in[3];
    const float* out_b = (const float*)d_in[4];
    float* out = (float*)d_out;

    cudaFuncSetAttribute(gemm_mma<0>, cudaFuncAttributeMaxDynamicSharedMemorySize, GEMM_SMEM);
    cudaFuncSetAttribute(gemm_mma<1>, cudaFuncAttributeMaxDynamicSharedMemorySize, GEMM_SMEM);
    cudaFuncSetAttribute(attn_mma, cudaFuncAttributeMaxDynamicSharedMemorySize, ATTN_SMEM);

    __half* xa; __half* wq; __half* wo;
    cudaGetSymbolAddress((void**)&xa, g_xa);
    cudaGetSymbolAddress((void**)&wq, g_wqkv);
    cudaGetSymbolAddress((void**)&wo, g_wout);

    // 0) round inputs to fp16 scratch
    cvt_kernel<<<(MROWS * EE / 4 + 255) / 256, 256>>>((const float4*)x, xa, MROWS * EE / 4);
    cvt_kernel<<<(3 * EE * EE / 4 + 255) / 256, 256>>>((const float4*)qkv_w, wq, 3 * EE * EE / 4);
    cvt_kernel<<<(EE * EE / 4 + 255) / 256, 256>>>((const float4*)out_w, wo, EE * EE / 4);

    // 1) fused QKV projection -> g_q (scaled) / g_khi,g_klo / g_v (fp16)
    gemm_mma<0><<<dim3(3072 / 128, MROWS / 128), 256, GEMM_SMEM>>>(qkv_b, nullptr, 3 * EE);

    // 2) causal flash attention -> g_att (fp16)
    attn_mma<<<dim3(SS / 128, BB * HH), 128, ATTN_SMEM>>>();

    // 3) output projection -> d_out (f32)
    gemm_mma<1><<<dim3(EE / 128, MROWS / 128), 256, GEMM_SMEM>>>(out_b, out, EE);
}